// round 10
// baseline (speedup 1.0000x reference)
#include <cuda_runtime.h>

#define NVERT 8192
#define GRES 64
#define NVOX (GRES*GRES*GRES)   // 262144
#define NMAX 1048576
#define SCANB 512               // 512 blocks x 512 threads covers NVOX

// ---------------- scratch (device globals; no allocation) ----------------
__device__ unsigned int g_mm[6];        // sortable-uint min(x,y,z), max(x,y,z)
__device__ int g_hist[NVOX];
__device__ int g_off[NVOX + 1];
__device__ int g_cur[NVOX];
__device__ int g_bsum[SCANB];
__device__ int g_bbase[SCANB];
__device__ int g_vid[NMAX];
__device__ float4 g_pts[NMAX];          // voxel-sorted points {x,y,z,bits(origidx)}
__device__ float4 g_vert[NVERT];        // raw {x, y, z, |v|^2}
// vertex grid for pruned knn
__device__ int v_hist[NVOX];
__device__ int v_off[NVOX + 1];
__device__ int v_cur[NVOX];
__device__ int v_cell[NVERT];
__device__ float4 g_vs[NVERT];          // cell-sorted, prescaled {2x,2y,2z,|v|^2}
__device__ unsigned short g_vsidx[NVERT];

// monotone float<->uint mapping (min/max via integer atomics)
__device__ __forceinline__ unsigned f2o(float f) {
    unsigned b = __float_as_uint(f);
    return (b & 0x80000000u) ? ~b : (b | 0x80000000u);
}
__device__ __forceinline__ float o2f(unsigned o) {
    unsigned b = (o & 0x80000000u) ? (o & 0x7FFFFFFFu) : ~o;
    return __uint_as_float(b);
}

// shared helper: per-axis extent guards (must match k_vidhist exactly)
__device__ __forceinline__ void grid_params(float& mnx, float& mny, float& mnz,
                                            float& dx, float& dy, float& dz) {
    mnx = o2f(g_mm[0]); mny = o2f(g_mm[1]); mnz = o2f(g_mm[2]);
    float exx = __fsub_rn(o2f(g_mm[3]), mnx);
    float exy = __fsub_rn(o2f(g_mm[4]), mny);
    float exz = __fsub_rn(o2f(g_mm[5]), mnz);
    dx = exx > 0.f ? exx : 1.f;
    dy = exy > 0.f ? exy : 1.f;
    dz = exz > 0.f ? exz : 1.f;
}

// ---------------- 2. global min/max per coordinate ----------------
__global__ void k_minmax(const float* __restrict__ xyz, int n) {
    float mnx = 3.402823466e38f, mny = mnx, mnz = mnx;
    float mxx = -3.402823466e38f, mxy = mxx, mxz = mxx;
    for (int i = blockIdx.x * blockDim.x + threadIdx.x; i < n;
         i += gridDim.x * blockDim.x) {
        float x = xyz[3 * i], y = xyz[3 * i + 1], z = xyz[3 * i + 2];
        mnx = fminf(mnx, x); mny = fminf(mny, y); mnz = fminf(mnz, z);
        mxx = fmaxf(mxx, x); mxy = fmaxf(mxy, y); mxz = fmaxf(mxz, z);
    }
    for (int o = 16; o; o >>= 1) {
        mnx = fminf(mnx, __shfl_xor_sync(0xFFFFFFFFu, mnx, o));
        mny = fminf(mny, __shfl_xor_sync(0xFFFFFFFFu, mny, o));
        mnz = fminf(mnz, __shfl_xor_sync(0xFFFFFFFFu, mnz, o));
        mxx = fmaxf(mxx, __shfl_xor_sync(0xFFFFFFFFu, mxx, o));
        mxy = fmaxf(mxy, __shfl_xor_sync(0xFFFFFFFFu, mxy, o));
        mxz = fmaxf(mxz, __shfl_xor_sync(0xFFFFFFFFu, mxz, o));
    }
    if ((threadIdx.x & 31) == 0) {
        atomicMin(&g_mm[0], f2o(mnx));
        atomicMin(&g_mm[1], f2o(mny));
        atomicMin(&g_mm[2], f2o(mnz));
        atomicMax(&g_mm[3], f2o(mxx));
        atomicMax(&g_mm[4], f2o(mxy));
        atomicMax(&g_mm[5], f2o(mxz));
    }
}

// ---------------- 3. voxel id + histogram (reciprocal-hoisted division) ----
__global__ void k_vidhist(const float* __restrict__ xyz, int n) {
    float mnx, mny, mnz, dx, dy, dz;
    grid_params(mnx, mny, mnz, dx, dy, dz);
    float rx = __fdiv_rn(1.0f, dx);
    float ry = __fdiv_rn(1.0f, dy);
    float rz = __fdiv_rn(1.0f, dz);
    const float HI = (float)(1.0 - 1e-6);
    for (int i = blockIdx.x * blockDim.x + threadIdx.x; i < n;
         i += gridDim.x * blockDim.x) {
        float ux = __fmul_rn(__fsub_rn(xyz[3 * i],     mnx), rx);
        float uy = __fmul_rn(__fsub_rn(xyz[3 * i + 1], mny), ry);
        float uz = __fmul_rn(__fsub_rn(xyz[3 * i + 2], mnz), rz);
        ux = fminf(fmaxf(ux, 0.f), HI);
        uy = fminf(fmaxf(uy, 0.f), HI);
        uz = fminf(fmaxf(uz, 0.f), HI);
        int vx = (int)floorf(__fmul_rn(ux, (float)GRES));
        int vy = (int)floorf(__fmul_rn(uy, (float)GRES));
        int vz = (int)floorf(__fmul_rn(uz, (float)GRES));
        int vid = (vx * GRES + vy) * GRES + vz;
        g_vid[i] = vid;
        atomicAdd(&g_hist[vid], 1);
    }
}

// ---------------- 4. generic exclusive scan over NVOX (3 kernels) ----------
__global__ void k_scan_a(const int* __restrict__ hist) {
    __shared__ int sh[512];
    int i = blockIdx.x * 512 + threadIdx.x;
    sh[threadIdx.x] = hist[i];
    __syncthreads();
    for (int off = 256; off; off >>= 1) {
        if (threadIdx.x < off) sh[threadIdx.x] += sh[threadIdx.x + off];
        __syncthreads();
    }
    if (threadIdx.x == 0) g_bsum[blockIdx.x] = sh[0];
}
__global__ void k_scan_b(int* __restrict__ off, int total) {
    __shared__ int sh[512];
    int v = g_bsum[threadIdx.x];
    sh[threadIdx.x] = v;
    __syncthreads();
    for (int o = 1; o < 512; o <<= 1) {
        int t = (threadIdx.x >= o) ? sh[threadIdx.x - o] : 0;
        __syncthreads();
        sh[threadIdx.x] += t;
        __syncthreads();
    }
    g_bbase[threadIdx.x] = sh[threadIdx.x] - v;
    if (threadIdx.x == 0) off[NVOX] = total;
}
__global__ void k_scan_c(const int* __restrict__ hist, int* __restrict__ off,
                         int* __restrict__ cur) {
    __shared__ int sh[512];
    int i = blockIdx.x * 512 + threadIdx.x;
    int v = hist[i];
    sh[threadIdx.x] = v;
    __syncthreads();
    for (int o = 1; o < 512; o <<= 1) {
        int t = (threadIdx.x >= o) ? sh[threadIdx.x - o] : 0;
        __syncthreads();
        sh[threadIdx.x] += t;
        __syncthreads();
    }
    int excl = sh[threadIdx.x] - v + g_bbase[blockIdx.x];
    off[i] = excl;
    cur[i] = excl;
}

// ---------------- 5. counting-sort scatter: packed point records -----------
__global__ void k_scatter(const float* __restrict__ xyz, int n) {
    for (int i = blockIdx.x * blockDim.x + threadIdx.x; i < n;
         i += gridDim.x * blockDim.x) {
        int v = g_vid[i];
        int pos = atomicAdd(&g_cur[v], 1);
        g_pts[pos] = make_float4(xyz[3 * i], xyz[3 * i + 1], xyz[3 * i + 2],
                                 __int_as_float(i));
    }
}

// ---------------- 6. stable selection of 8192 vertices (+ vertex binning) --
// sel per f32 jnp.linspace: delta = RN((n-1)/8191); s = floor(RN(q*delta)).
__global__ void k_select(float* __restrict__ out, int n) {
    __shared__ int sb[4096];
    __shared__ int info[3];
    int q = blockIdx.x;
    if (threadIdx.x == 0) {
        float delta = __fdiv_rn((float)(n - 1), (float)(NVERT - 1));
        float fv = __fmul_rn((float)q, delta);
        int s = (int)floorf(fv);
        int lo = 0, hi = NVOX;
        while (hi - lo > 1) {
            int mid = (lo + hi) >> 1;
            if (g_off[mid] <= s) lo = mid; else hi = mid;
        }
        info[0] = g_off[lo];
        info[1] = g_off[lo + 1] - g_off[lo];
        info[2] = s - g_off[lo];
    }
    __syncthreads();
    int base = info[0], m = info[1], r = info[2];

    float mnx, mny, mnz, dx, dy, dz;
    grid_params(mnx, mny, mnz, dx, dy, dz);
    float ivx = __fdiv_rn((float)GRES, dx);
    float ivy = __fdiv_rn((float)GRES, dy);
    float ivz = __fdiv_rn((float)GRES, dz);

    if (m <= 4096) {
        for (int j = threadIdx.x; j < m; j += blockDim.x)
            sb[j] = __float_as_int(g_pts[base + j].w);
        __syncthreads();
        for (int j = threadIdx.x; j < m; j += blockDim.x) {
            int x = sb[j], c = 0;
            for (int t = 0; t < m; t++) c += (sb[t] < x);
            if (c == r) {
                float4 P = g_pts[base + j];
                out[3 * q] = P.x; out[3 * q + 1] = P.y; out[3 * q + 2] = P.z;
                float vn = __fadd_rn(__fadd_rn(__fmul_rn(P.x, P.x), __fmul_rn(P.y, P.y)),
                                     __fmul_rn(P.z, P.z));
                g_vert[q] = make_float4(P.x, P.y, P.z, vn);
                int cx = min(max((int)floorf((P.x - mnx) * ivx), 0), GRES - 1);
                int cy = min(max((int)floorf((P.y - mny) * ivy), 0), GRES - 1);
                int cz = min(max((int)floorf((P.z - mnz) * ivz), 0), GRES - 1);
                int cell = (cx * GRES + cy) * GRES + cz;
                v_cell[q] = cell;
                atomicAdd(&v_hist[cell], 1);
            }
        }
    } else {
        for (int j = threadIdx.x; j < m; j += blockDim.x) {
            int x = __float_as_int(g_pts[base + j].w), c = 0;
            for (int t = 0; t < m; t++)
                c += (__float_as_int(g_pts[base + t].w) < x);
            if (c == r) {
                float4 P = g_pts[base + j];
                out[3 * q] = P.x; out[3 * q + 1] = P.y; out[3 * q + 2] = P.z;
                float vn = __fadd_rn(__fadd_rn(__fmul_rn(P.x, P.x), __fmul_rn(P.y, P.y)),
                                     __fmul_rn(P.z, P.z));
                g_vert[q] = make_float4(P.x, P.y, P.z, vn);
                int cx = min(max((int)floorf((P.x - mnx) * ivx), 0), GRES - 1);
                int cy = min(max((int)floorf((P.y - mny) * ivy), 0), GRES - 1);
                int cz = min(max((int)floorf((P.z - mnz) * ivz), 0), GRES - 1);
                int cell = (cx * GRES + cy) * GRES + cz;
                v_cell[q] = cell;
                atomicAdd(&v_hist[cell], 1);
            }
        }
    }
}

// ---------------- 6c. scatter vertices (prescaled by 2) --------------------
__global__ void k_vscatter() {
    int q = blockIdx.x * blockDim.x + threadIdx.x;
    if (q >= NVERT) return;
    int c = v_cell[q];
    int pos = atomicAdd(&v_cur[c], 1);
    float4 v = g_vert[q];
    g_vs[pos] = make_float4(2.0f * v.x, 2.0f * v.y, 2.0f * v.z, v.w);
    g_vsidx[pos] = (unsigned short)q;
}

// exact reference-formula eval + lexicographic (d, oi) min update
#define EVAL_EXACT(J)                                                          \
    do {                                                                       \
        float4 V = sv[J];                                                      \
        float t2 = fmaf(pz, V.z, fmaf(py, V.y, __fmul_rn(px, V.x)));           \
        float d = __fsub_rn(V.w, t2);                                          \
        int oi = sidx[J];                                                      \
        if (d < bd || (d == bd && oi < bi)) { bd = d; bi = oi; }               \
    } while (0)

// ---------------- 7. merged grid-pruned 1-NN with containment skip ---------
// Octant 2^3 box scanned ONCE with the exact reference formula; radius
// R^2 = max(bd+pn,0)+1e-3 (same magnitude as the R8/R9 passing margin,
// since bd+pn == geometric D^2 up to ~1e-6). If the sphere box is inside
// the scanned box -> done (~65% of points). Else rescan the full sphere
// box (idempotent under the lexicographic comparator).
__global__ void __launch_bounds__(1024, 1)
k_knn(float* __restrict__ out, int n) {
    extern __shared__ char smem[];
    float4* sv = (float4*)smem;                         // 8192 * 16B
    unsigned short* sidx = (unsigned short*)(smem + NVERT * sizeof(float4));
    for (int j = threadIdx.x; j < NVERT; j += blockDim.x) {
        sv[j] = g_vs[j];
        sidx[j] = g_vsidx[j];
    }
    __syncthreads();

    float mnx, mny, mnz, dx, dy, dz;
    grid_params(mnx, mny, mnz, dx, dy, dz);
    float ivx = __fdiv_rn((float)GRES, dx);
    float ivy = __fdiv_rn((float)GRES, dy);
    float ivz = __fdiv_rn((float)GRES, dz);
    float* pout = out + 3 * NVERT;

    for (int i = blockIdx.x * blockDim.x + threadIdx.x; i < n;
         i += gridDim.x * blockDim.x) {
        float4 P = g_pts[i];                // coalesced stream
        float px = P.x, py = P.y, pz = P.z;
        int p = __float_as_int(P.w);
        float fx = (px - mnx) * ivx, fy = (py - mny) * ivy, fz = (pz - mnz) * ivz;
        int cx = min(max((int)floorf(fx), 0), GRES - 1);
        int cy = min(max((int)floorf(fy), 0), GRES - 1);
        int cz = min(max((int)floorf(fz), 0), GRES - 1);
        float pn = fmaf(pz, pz, fmaf(py, py, px * px));

        float bd = 3.402823466e38f;
        int bi = 0x7FFFFFFF;

        // ---- octant 2^3 box, exact formula, bounds prefetched (MLP=8) ----
        int ox0 = (fx - (float)cx > 0.5f) ? cx : cx - 1;
        int oy0 = (fy - (float)cy > 0.5f) ? cy : cy - 1;
        int oz0 = (fz - (float)cz > 0.5f) ? cz : cz - 1;
        ox0 = max(ox0, 0); int ox1 = min(ox0 + 1, GRES - 1); ox0 = min(ox0, ox1);
        oy0 = max(oy0, 0); int oy1 = min(oy0 + 1, GRES - 1); oy0 = min(oy0, oy1);
        oz0 = max(oz0, 0); int oz1 = min(oz0 + 1, GRES - 1); oz0 = min(oz0, oz1);
        {
            int r00 = (ox0 * GRES + oy0) * GRES;
            int r01 = (ox0 * GRES + oy1) * GRES;
            int r10 = (ox1 * GRES + oy0) * GRES;
            int r11 = (ox1 * GRES + oy1) * GRES;
            int s00 = v_off[r00 + oz0], e00 = v_off[r00 + oz1 + 1];
            int s01 = v_off[r01 + oz0], e01 = v_off[r01 + oz1 + 1];
            int s10 = v_off[r10 + oz0], e10 = v_off[r10 + oz1 + 1];
            int s11 = v_off[r11 + oz0], e11 = v_off[r11 + oz1 + 1];
            #pragma unroll 1
            for (int j = s00; j < e00; j++) EVAL_EXACT(j);
            #pragma unroll 1
            for (int j = s01; j < e01; j++) EVAL_EXACT(j);
            #pragma unroll 1
            for (int j = s10; j < e10; j++) EVAL_EXACT(j);
            #pragma unroll 1
            for (int j = s11; j < e11; j++) EVAL_EXACT(j);
        }
        // rare fallback: expanding boxes (exact formula) until a vertex found
        if (bi == 0x7FFFFFFF) {
            for (int w = 1; w < GRES; w++) {
                ox0 = max(cx - w, 0); ox1 = min(cx + w, GRES - 1);
                oy0 = max(cy - w, 0); oy1 = min(cy + w, GRES - 1);
                oz0 = max(cz - w, 0); oz1 = min(cz + w, GRES - 1);
                for (int ix = ox0; ix <= ox1; ix++)
                    for (int iy = oy0; iy <= oy1; iy++) {
                        int row = (ix * GRES + iy) * GRES;
                        int s = v_off[row + oz0];
                        int e = v_off[row + oz1 + 1];
                        for (int j = s; j < e; j++) EVAL_EXACT(j);
                    }
                if (bi != 0x7FFFFFFF) break;
            }
        }

        // ---- radius from exact bd (== geometric D^2 up to ~1e-6) ----
        float R = sqrtf(fmaxf(bd + pn, 0.0f) + 1e-3f) + 1e-3f;
        int x0 = min(max((int)floorf((px - R - mnx) * ivx), 0), GRES - 1);
        int x1 = min(max((int)floorf((px + R - mnx) * ivx), 0), GRES - 1);
        int y0 = min(max((int)floorf((py - R - mny) * ivy), 0), GRES - 1);
        int y1 = min(max((int)floorf((py + R - mny) * ivy), 0), GRES - 1);
        int z0 = min(max((int)floorf((pz - R - mnz) * ivz), 0), GRES - 1);
        int z1 = min(max((int)floorf((pz + R - mnz) * ivz), 0), GRES - 1);

        // containment: sphere box inside the already-scanned box -> done
        if (x0 < ox0 || x1 > ox1 || y0 < oy0 || y1 > oy1 ||
            z0 < oz0 || z1 > oz1) {
            // full sphere-box rescan, 1-ahead row prefetch (idempotent)
            int ny = y1 - y0 + 1;
            int nr = (x1 - x0 + 1) * ny;
            int ix = x0, iy = y0;
            int rowb = (ix * GRES + iy) * GRES;
            int sC = v_off[rowb + z0], eC = v_off[rowb + z1 + 1];
            for (int r = 0; r < nr; r++) {
                int nix = ix, niy = iy + 1;
                if (niy > y1) { niy = y0; nix = ix + 1; }
                int sN = 0, eN = 0;
                if (r + 1 < nr) {
                    int nb = (nix * GRES + niy) * GRES;
                    sN = v_off[nb + z0];
                    eN = v_off[nb + z1 + 1];
                }
                #pragma unroll 1
                for (int j = sC; j < eC; j++) EVAL_EXACT(j);
                sC = sN; eC = eN; ix = nix; iy = niy;
            }
        }
        pout[p] = (float)bi;
    }
}

// ---------------- launch ----------------
extern "C" void kernel_launch(void* const* d_in, const int* in_sizes, int n_in,
                              void* d_out, int out_size) {
    const float* xyz = (const float*)d_in[0];
    int n = in_sizes[0] / 3;
    float* out = (float*)d_out;

    int* d_ghist; cudaGetSymbolAddress((void**)&d_ghist, g_hist);
    int* d_goff;  cudaGetSymbolAddress((void**)&d_goff,  g_off);
    int* d_gcur;  cudaGetSymbolAddress((void**)&d_gcur,  g_cur);
    int* d_vhist; cudaGetSymbolAddress((void**)&d_vhist, v_hist);
    int* d_voff;  cudaGetSymbolAddress((void**)&d_voff,  v_off);
    int* d_vcur;  cudaGetSymbolAddress((void**)&d_vcur,  v_cur);
    unsigned int* d_mm; cudaGetSymbolAddress((void**)&d_mm, g_mm);

    // init via memset nodes
    cudaMemsetAsync(d_ghist, 0, NVOX * sizeof(int));
    cudaMemsetAsync(d_vhist, 0, NVOX * sizeof(int));
    cudaMemsetAsync(d_mm, 0xFF, 3 * sizeof(unsigned int));
    cudaMemsetAsync(d_mm + 3, 0x00, 3 * sizeof(unsigned int));

    k_minmax<<<148, 256>>>(xyz, n);
    k_vidhist<<<1024, 256>>>(xyz, n);
    k_scan_a<<<SCANB, 512>>>(d_ghist);
    k_scan_b<<<1, 512>>>(d_goff, n);
    k_scan_c<<<SCANB, 512>>>(d_ghist, d_goff, d_gcur);
    k_scatter<<<1024, 256>>>(xyz, n);
    k_select<<<NVERT, 128>>>(out, n);
    k_scan_a<<<SCANB, 512>>>(d_vhist);
    k_scan_b<<<1, 512>>>(d_voff, NVERT);
    k_scan_c<<<SCANB, 512>>>(d_vhist, d_voff, d_vcur);
    k_vscatter<<<16, 512>>>();

    int smem = NVERT * (int)sizeof(float4) + NVERT * (int)sizeof(unsigned short);
    cudaFuncSetAttribute(k_knn, cudaFuncAttributeMaxDynamicSharedMemorySize, smem);
    k_knn<<<148, 1024, smem>>>(out, n);
}